// round 3
// baseline (speedup 1.0000x reference)
#include <cuda_runtime.h>
#include <cuda_bf16.h>
#include <math.h>

// Accumulators: [0]=focal_sum, [1]=iou_pos_sum, [2]=npos, [3]=rcnn_sum, [4]=pcnt_total
// Zero at module load; the last finishing block resets them after reading, so
// every launch / graph replay starts from zero. Deterministic.
__device__ double g_acc[5];
__device__ unsigned int g_done;   // completion counter, reset by last block

#define RPN_BLOCKS 1184   // 148 SMs * 8
#define THREADS 256

__device__ __forceinline__ float blk_reduce(float v, float* sh) {
    int lane = threadIdx.x & 31, wid = threadIdx.x >> 5;
    #pragma unroll
    for (int o = 16; o; o >>= 1) v += __shfl_down_sync(0xffffffffu, v, o);
    if (lane == 0) sh[wid] = v;
    __syncthreads();
    int nw = (blockDim.x + 31) >> 5;
    v = (threadIdx.x < nw) ? sh[threadIdx.x] : 0.0f;
    if (wid == 0) {
        #pragma unroll
        for (int o = 16; o; o >>= 1) v += __shfl_down_sync(0xffffffffu, v, o);
    }
    __syncthreads();
    return v;
}

__global__ __launch_bounds__(THREADS)
void fused_kernel(const float2* __restrict__ cl,
                  const float4* __restrict__ re,
                  const float4* __restrict__ gr,
                  const float*  __restrict__ gt,
                  const float*  __restrict__ cf,
                  const float*  __restrict__ op,
                  const float4* __restrict__ bb,
                  const float4* __restrict__ br,
                  const float4* __restrict__ gb,
                  float* __restrict__ out, int out_size,
                  int total, int N, int K, int B) {
    __shared__ float sh[32];

    if (blockIdx.x < (unsigned)B) {
        // ---------------- RCNN: one block per batch ----------------
        int b = blockIdx.x;
        float4 g = gb[b];
        float area_a = (g.z - g.x) * (g.w - g.y);

        float pcnt = 0.f, ncnt = 0.f;
        float s_pp = 0.f, s_pn = 0.f, s_ng = 0.f, s_op = 0.f, s_bb = 0.f;

        size_t base = (size_t)b * (size_t)N;
        int halfK = K >> 1;
        for (int n = threadIdx.x; n < N; n += blockDim.x) {
            float4 r = br[base + n];
            float lt0 = fmaxf(g.x, r.x), lt1 = fmaxf(g.y, r.y);
            float rb0 = fminf(g.z, r.z), rb1 = fminf(g.w, r.w);
            float w = fmaxf(rb0 - lt0, 0.0f), h = fmaxf(rb1 - lt1, 0.0f);
            float inter = w * h;
            float area_b = (r.z - r.x) * (r.w - r.y);
            float iou = __fdividef(inter + 1e-7f, area_a + area_b - inter + 1e-7f);
            bool pos = (iou >= 0.5f);
            bool neg = (iou <  0.4f);
            if (pos || neg) {
                const float4* rp = reinterpret_cast<const float4*>(cf)
                                 + (base + (size_t)n) * (size_t)halfK;
                float4 v0 = rp[0];
                float d0 = v0.x - v0.y;
                float t0 = __expf(-fabsf(d0));
                float l0 = __logf(1.0f + t0);
                if (pos) s_pp += fmaxf(-d0, 0.0f) + l0;
                if (neg) { s_pn += fmaxf(d0, 0.0f) + l0; ncnt += 1.0f; }
                if (pos) {
                    pcnt += 1.0f;
                    {
                        float d = v0.z - v0.w;
                        s_ng += fmaxf(d, 0.0f) + __logf(1.0f + __expf(-fabsf(d)));
                    }
                    #pragma unroll 7
                    for (int j = 1; j < halfK; ++j) {
                        float4 v = rp[j];
                        float da = v.x - v.y;
                        s_ng += fmaxf(da, 0.0f) + __logf(1.0f + __expf(-fabsf(da)));
                        float db = v.z - v.w;
                        s_ng += fmaxf(db, 0.0f) + __logf(1.0f + __expf(-fabsf(db)));
                    }
                    float x = op[base + n];
                    s_op += fmaxf(x, 0.0f) - x * iou
                          + __logf(1.0f + __expf(-fabsf(x)));

                    float4 bx = bb[base + n];
                    float l0b = fmaxf(g.x, bx.x), l1b = fmaxf(g.y, bx.y);
                    float r0b = fminf(g.z, bx.z), r1b = fminf(g.w, bx.w);
                    float ww = fmaxf(r0b - l0b, 0.0f), hh = fmaxf(r1b - l1b, 0.0f);
                    float in2 = ww * hh;
                    float ab2 = (bx.z - bx.x) * (bx.w - bx.y);
                    float iou2 = __fdividef(in2 + 1.0f, area_a + ab2 - in2 + 1.0f);
                    s_bb += 1.0f - iou2;
                }
            }
        }

        pcnt = blk_reduce(pcnt, sh);
        ncnt = blk_reduce(ncnt, sh);
        s_pp = blk_reduce(s_pp, sh);
        s_pn = blk_reduce(s_pn, sh);
        s_ng = blk_reduce(s_ng, sh);
        s_op = blk_reduce(s_op, sh);
        s_bb = blk_reduce(s_bb, sh);

        if (threadIdx.x == 0) {
            float l_pp = (pcnt > 0.f) ? s_pp / fmaxf(pcnt, 1.0f) : 0.0f;
            float l_pn = (ncnt > 0.f) ? s_pn / fmaxf(ncnt, 1.0f) : 0.0f;
            float l_ng = (pcnt > 0.f) ? s_ng / fmaxf(pcnt * (float)(K - 1), 1.0f) : 0.0f;
            float l_op = (pcnt > 0.f) ? s_op / fmaxf(pcnt, 1.0f) : 0.0f;
            float l_bb = (pcnt > 0.f) ? s_bb / fmaxf(pcnt, 1.0f) : 0.0f;
            float loss_i = (pcnt > 0.f) ? (l_pp + l_pn + l_ng + l_bb + l_op) : 0.0f;
            atomicAdd(&g_acc[3], (double)loss_i);
            atomicAdd(&g_acc[4], (double)pcnt);
        }
    } else {
        // ---------------- RPN: grid-stride over B*HW anchors ----------------
        int tid = (blockIdx.x - B) * blockDim.x + threadIdx.x;
        int stride = RPN_BLOCKS * blockDim.x;
        float a0 = 0.f, a1 = 0.f, a2 = 0.f;
        #pragma unroll 8
        for (int i = tid; i < total; i += stride) {
            float2 c = cl[i];
            float gv = gt[i];
            float4 r = re[i], G = gr[i];

            bool posg = gv > 0.0f;
            float s = posg ? (c.x - c.y) : (c.y - c.x);
            float t = __expf(-fabsf(s));
            float l = __logf(1.0f + t);
            float logpt = fminf(s, 0.0f) - l;
            float pt = __expf(logpt);
            float at = posg ? 0.25f : 0.75f;
            float om = 1.0f - pt;
            a0 += -om * om * at * logpt;

            float mn0 = fminf(r.x, G.x), mn1 = fminf(r.y, G.y);
            float mn2 = fminf(r.z, G.z), mn3 = fminf(r.w, G.w);
            float inter = (mn0 + mn2) * (mn1 + mn3);
            float ag = (G.x + G.z) * (G.y + G.w);
            float ar = (r.x + r.z) * (r.y + r.w);
            float un = ag + ar - inter + 1e-7f;
            float iou = __fdividef(inter + 1.0f, un + 1.0f);
            if (posg) { a1 += 1.0f - iou; a2 += 1.0f; }
        }
        a0 = blk_reduce(a0, sh);
        a1 = blk_reduce(a1, sh);
        a2 = blk_reduce(a2, sh);
        if (threadIdx.x == 0) {
            atomicAdd(&g_acc[0], (double)a0);
            atomicAdd(&g_acc[1], (double)a1);
            atomicAdd(&g_acc[2], (double)a2);
        }
    }

    // ---------------- inline finalize: last block does it ----------------
    __shared__ unsigned int s_ticket;
    if (threadIdx.x == 0) {
        __threadfence();
        s_ticket = atomicAdd(&g_done, 1u);
    }
    __syncthreads();
    if (s_ticket == gridDim.x - 1) {
        // zero output tail cooperatively
        for (int i = 5 + threadIdx.x; i < out_size; i += blockDim.x) out[i] = 0.0f;
        if (threadIdx.x == 0) {
            double rpn0 = g_acc[0] / (double)total;
            double np   = g_acc[2];
            double rpn1 = (np > 0.0) ? g_acc[1] / fmax(np, 1.0) : 0.0;
            double rcnn = g_acc[3] / (double)B;
            out[0] = (float)(rpn0 + rpn1 + rcnn);
            out[1] = (float)rpn0;
            out[2] = (float)rpn1;
            out[3] = (float)rcnn;
            out[4] = (float)((long long)(g_acc[4] + 0.5));
            // reset for next call / graph replay
            g_acc[0] = 0.0; g_acc[1] = 0.0; g_acc[2] = 0.0;
            g_acc[3] = 0.0; g_acc[4] = 0.0;
            __threadfence();
            g_done = 0u;
        }
    }
}

extern "C" void kernel_launch(void* const* d_in, const int* in_sizes, int n_in,
                              void* d_out, int out_size) {
    const float* cl = (const float*)d_in[0];   // (B,HW,2)
    const float* re = (const float*)d_in[1];   // (B,HW,4)
    const float* cf = (const float*)d_in[2];   // (B,N,K,2)
    const float* op = (const float*)d_in[3];   // (B,N,1)
    const float* bb = (const float*)d_in[4];   // (B,N,4)
    const float* br = (const float*)d_in[5];   // (B,N,4)
    const float* gb = (const float*)d_in[6];   // (B,4)
    const float* gt = (const float*)d_in[7];   // (B,HW)
    const float* gr = (const float*)d_in[8];   // (B,HW,4)

    int B  = in_sizes[6] / 4;
    int HW = in_sizes[7] / B;
    int N  = in_sizes[3] / B;
    int K  = in_sizes[2] / (B * N * 2);
    int total = B * HW;

    fused_kernel<<<B + RPN_BLOCKS, THREADS>>>(
        (const float2*)cl, (const float4*)re, (const float4*)gr, gt,
        cf, op, (const float4*)bb, (const float4*)br, (const float4*)gb,
        (float*)d_out, out_size, total, N, K, B);
}

// round 4
// speedup vs baseline: 1.2653x; 1.2653x over previous
#include <cuda_runtime.h>
#include <cuda_bf16.h>
#include <math.h>

// Global scratch (zero at module load; finalize restores zeros every call, so
// graph replays are deterministic).
__device__ double g_acc[3];            // [0]=focal_sum [1]=iou_pos_sum [2]=npos
__device__ float  g_batch[256 * 8];    // per-batch partials: pc,nc,pp,pn,ng,op,bb
__device__ unsigned int g_done;

#define THREADS 256
#define RCNN_SPLIT 2

__device__ __forceinline__ float blk_reduce(float v, float* sh) {
    int lane = threadIdx.x & 31, wid = threadIdx.x >> 5;
    #pragma unroll
    for (int o = 16; o; o >>= 1) v += __shfl_down_sync(0xffffffffu, v, o);
    if (lane == 0) sh[wid] = v;
    __syncthreads();
    int nw = (blockDim.x + 31) >> 5;
    v = (threadIdx.x < nw) ? sh[threadIdx.x] : 0.0f;
    if (wid == 0) {
        #pragma unroll
        for (int o = 16; o; o >>= 1) v += __shfl_down_sync(0xffffffffu, v, o);
    }
    __syncthreads();
    return v;
}

__global__ __launch_bounds__(THREADS, 6)
void fused_kernel(const float2* __restrict__ cl,
                  const float4* __restrict__ re,
                  const float4* __restrict__ gr,
                  const float*  __restrict__ gt,
                  const float*  __restrict__ cf,
                  const float*  __restrict__ op,
                  const float4* __restrict__ bb,
                  const float4* __restrict__ br,
                  const float4* __restrict__ gb,
                  float* __restrict__ out, int out_size,
                  int total, int N, int K, int B,
                  int rcnn_blocks, int rpn_blocks) {
    __shared__ float sh[32];

    if (blockIdx.x < (unsigned)rcnn_blocks) {
        // ------------- RCNN: RCNN_SPLIT blocks per batch -------------
        int b    = blockIdx.x / RCNN_SPLIT;
        int part = blockIdx.x % RCNN_SPLIT;
        int chunk = N / RCNN_SPLIT;
        int n0 = part * chunk, n1 = n0 + chunk;

        float4 g = gb[b];
        float area_a = (g.z - g.x) * (g.w - g.y);

        float pcnt = 0.f, ncnt = 0.f;
        float s_pp = 0.f, s_pn = 0.f, s_ng = 0.f, s_op = 0.f, s_bb = 0.f;

        size_t base = (size_t)b * (size_t)N;
        int halfK = K >> 1;
        for (int n = n0 + threadIdx.x; n < n1; n += THREADS) {
            float4 r = br[base + n];
            float lt0 = fmaxf(g.x, r.x), lt1 = fmaxf(g.y, r.y);
            float rb0 = fminf(g.z, r.z), rb1 = fminf(g.w, r.w);
            float w = fmaxf(rb0 - lt0, 0.0f), h = fmaxf(rb1 - lt1, 0.0f);
            float inter = w * h;
            float area_b = (r.z - r.x) * (r.w - r.y);
            float iou = __fdividef(inter + 1e-7f, area_a + area_b - inter + 1e-7f);
            bool pos = (iou >= 0.5f);
            bool neg = (iou <  0.4f);
            if (pos || neg) {
                const float4* rp = reinterpret_cast<const float4*>(cf)
                                 + (base + (size_t)n) * (size_t)halfK;
                float4 v0 = rp[0];
                float d0 = v0.x - v0.y;
                float l0 = __logf(1.0f + __expf(-fabsf(d0)));
                if (pos) s_pp += fmaxf(-d0, 0.0f) + l0;
                if (neg) { s_pn += fmaxf(d0, 0.0f) + l0; ncnt += 1.0f; }
                if (pos) {
                    pcnt += 1.0f;
                    {
                        float d = v0.z - v0.w;
                        s_ng += fmaxf(d, 0.0f) + __logf(1.0f + __expf(-fabsf(d)));
                    }
                    #pragma unroll 7
                    for (int j = 1; j < halfK; ++j) {
                        float4 v = rp[j];
                        float da = v.x - v.y;
                        s_ng += fmaxf(da, 0.0f) + __logf(1.0f + __expf(-fabsf(da)));
                        float db = v.z - v.w;
                        s_ng += fmaxf(db, 0.0f) + __logf(1.0f + __expf(-fabsf(db)));
                    }
                    float x = op[base + n];
                    s_op += fmaxf(x, 0.0f) - x * iou
                          + __logf(1.0f + __expf(-fabsf(x)));

                    float4 bx = bb[base + n];
                    float l0b = fmaxf(g.x, bx.x), l1b = fmaxf(g.y, bx.y);
                    float r0b = fminf(g.z, bx.z), r1b = fminf(g.w, bx.w);
                    float ww = fmaxf(r0b - l0b, 0.0f), hh = fmaxf(r1b - l1b, 0.0f);
                    float in2 = ww * hh;
                    float ab2 = (bx.z - bx.x) * (bx.w - bx.y);
                    float iou2 = __fdividef(in2 + 1.0f, area_a + ab2 - in2 + 1.0f);
                    s_bb += 1.0f - iou2;
                }
            }
        }

        pcnt = blk_reduce(pcnt, sh);
        ncnt = blk_reduce(ncnt, sh);
        s_pp = blk_reduce(s_pp, sh);
        s_pn = blk_reduce(s_pn, sh);
        s_ng = blk_reduce(s_ng, sh);
        s_op = blk_reduce(s_op, sh);
        s_bb = blk_reduce(s_bb, sh);

        if (threadIdx.x == 0) {
            float* gp = &g_batch[b * 8];
            atomicAdd(gp + 0, pcnt);
            atomicAdd(gp + 1, ncnt);
            atomicAdd(gp + 2, s_pp);
            atomicAdd(gp + 3, s_pn);
            atomicAdd(gp + 4, s_ng);
            atomicAdd(gp + 5, s_op);
            atomicAdd(gp + 6, s_bb);
        }
    } else {
        // ------------- RPN: grid-stride over B*HW anchors -------------
        int tid = (blockIdx.x - rcnn_blocks) * THREADS + threadIdx.x;
        int stride = rpn_blocks * THREADS;
        float a0 = 0.f, a1 = 0.f, a2 = 0.f;
        for (int i = tid; i < total; i += stride) {
            float2 c = cl[i];
            float gv = gt[i];
            float4 r = re[i], G = gr[i];

            bool posg = gv > 0.0f;
            float s = posg ? (c.x - c.y) : (c.y - c.x);
            float l = __logf(1.0f + __expf(-fabsf(s)));
            float logpt = fminf(s, 0.0f) - l;
            float pt = __expf(logpt);
            float at = posg ? 0.25f : 0.75f;
            float om = 1.0f - pt;
            a0 += -om * om * at * logpt;

            float mn0 = fminf(r.x, G.x), mn1 = fminf(r.y, G.y);
            float mn2 = fminf(r.z, G.z), mn3 = fminf(r.w, G.w);
            float inter = (mn0 + mn2) * (mn1 + mn3);
            float ag = (G.x + G.z) * (G.y + G.w);
            float ar = (r.x + r.z) * (r.y + r.w);
            float un = ag + ar - inter + 1e-7f;
            float iou = __fdividef(inter + 1.0f, un + 1.0f);
            if (posg) { a1 += 1.0f - iou; a2 += 1.0f; }
        }
        a0 = blk_reduce(a0, sh);
        a1 = blk_reduce(a1, sh);
        a2 = blk_reduce(a2, sh);
        if (threadIdx.x == 0) {
            atomicAdd(&g_acc[0], (double)a0);
            atomicAdd(&g_acc[1], (double)a1);
            atomicAdd(&g_acc[2], (double)a2);
        }
    }

    // ------------- last block: finalize + reset -------------
    __shared__ unsigned int s_ticket;
    if (threadIdx.x == 0) {
        __threadfence();
        s_ticket = atomicAdd(&g_done, 1u);
    }
    __syncthreads();
    if (s_ticket == gridDim.x - 1) {
        __threadfence();
        // per-batch loss_i from partials (threads 0..B-1)
        float loss_i = 0.f, pc_tot = 0.f;
        if (threadIdx.x < B) {
            volatile float* gp = &g_batch[threadIdx.x * 8];
            float pc = gp[0], nc = gp[1];
            float pp = gp[2], pn = gp[3], ng = gp[4], ov = gp[5], bv = gp[6];
            if (pc > 0.f) {
                float inv_pc = 1.0f / fmaxf(pc, 1.0f);
                float l_pp = pp * inv_pc;
                float l_pn = (nc > 0.f) ? pn / fmaxf(nc, 1.0f) : 0.0f;
                float l_ng = ng / fmaxf(pc * (float)(K - 1), 1.0f);
                float l_op = ov * inv_pc;
                float l_bb = bv * inv_pc;
                loss_i = l_pp + l_pn + l_ng + l_bb + l_op;
            }
            pc_tot = pc;
            // reset partials for next replay
            gp[0] = 0.f; gp[1] = 0.f; gp[2] = 0.f; gp[3] = 0.f;
            gp[4] = 0.f; gp[5] = 0.f; gp[6] = 0.f; gp[7] = 0.f;
        }
        float rcnn_sum = blk_reduce(loss_i, sh);
        float pcnt_tot = blk_reduce(pc_tot, sh);

        for (int i = 5 + threadIdx.x; i < out_size; i += THREADS) out[i] = 0.0f;

        if (threadIdx.x == 0) {
            volatile double* ga = g_acc;
            double rpn0 = ga[0] / (double)total;
            double np   = ga[2];
            double rpn1 = (np > 0.0) ? ga[1] / fmax(np, 1.0) : 0.0;
            double rcnn = (double)rcnn_sum / (double)B;
            out[0] = (float)(rpn0 + rpn1 + rcnn);
            out[1] = (float)rpn0;
            out[2] = (float)rpn1;
            out[3] = (float)rcnn;
            out[4] = (float)((long long)((double)pcnt_tot + 0.5));
            g_acc[0] = 0.0; g_acc[1] = 0.0; g_acc[2] = 0.0;
            __threadfence();
            g_done = 0u;
        }
    }
}

extern "C" void kernel_launch(void* const* d_in, const int* in_sizes, int n_in,
                              void* d_out, int out_size) {
    const float* cl = (const float*)d_in[0];   // (B,HW,2)
    const float* re = (const float*)d_in[1];   // (B,HW,4)
    const float* cf = (const float*)d_in[2];   // (B,N,K,2)
    const float* op = (const float*)d_in[3];   // (B,N,1)
    const float* bb = (const float*)d_in[4];   // (B,N,4)
    const float* br = (const float*)d_in[5];   // (B,N,4)
    const float* gb = (const float*)d_in[6];   // (B,4)
    const float* gt = (const float*)d_in[7];   // (B,HW)
    const float* gr = (const float*)d_in[8];   // (B,HW,4)

    int B  = in_sizes[6] / 4;
    int HW = in_sizes[7] / B;
    int N  = in_sizes[3] / B;
    int K  = in_sizes[2] / (B * N * 2);
    int total = B * HW;

    // single resident wave: 148 SMs * 6 CTAs (launch_bounds 256,6)
    int rcnn_blocks = B * RCNN_SPLIT;            // 256
    int grid = 148 * 6;                          // 888
    if (grid < rcnn_blocks + 128) grid = rcnn_blocks + 128;
    int rpn_blocks = grid - rcnn_blocks;         // 632

    fused_kernel<<<grid, THREADS>>>(
        (const float2*)cl, (const float4*)re, (const float4*)gr, gt,
        cf, op, (const float4*)bb, (const float4*)br, (const float4*)gb,
        (float*)d_out, out_size, total, N, K, B, rcnn_blocks, rpn_blocks);
}